// round 1
// baseline (speedup 1.0000x reference)
#include <cuda_runtime.h>

// Per-row cosine scratch (allocation-free: __device__ global).
__device__ float g_row_cos[8192];

#define NROWS 8192
#define D 512
#define D4 (D / 4)   // 128 float4 per row

__global__ __launch_bounds__(256) void byol_rowcos_kernel(
    const float4* __restrict__ x, const float4* __restrict__ xt)
{
    int gwarp = (blockIdx.x * blockDim.x + threadIdx.x) >> 5;  // row index
    int lane  = threadIdx.x & 31;
    if (gwarp >= NROWS) return;

    const float4* xr = x  + (size_t)gwarp * D4;
    const float4* tr = xt + (size_t)gwarp * D4;

    float dot = 0.f, nx = 0.f, nt = 0.f;
    #pragma unroll
    for (int i = 0; i < 4; i++) {
        float4 a = xr[lane + i * 32];
        float4 b = tr[lane + i * 32];
        dot += a.x * b.x + a.y * b.y + a.z * b.z + a.w * b.w;
        nx  += a.x * a.x + a.y * a.y + a.z * a.z + a.w * a.w;
        nt  += b.x * b.x + b.y * b.y + b.z * b.z + b.w * b.w;
    }

    // Warp tree reduction (deterministic order).
    #pragma unroll
    for (int off = 16; off > 0; off >>= 1) {
        dot += __shfl_xor_sync(0xffffffffu, dot, off);
        nx  += __shfl_xor_sync(0xffffffffu, nx,  off);
        nt  += __shfl_xor_sync(0xffffffffu, nt,  off);
    }

    if (lane == 0) {
        const float EPS = 1e-8f;
        float denom = fmaxf(sqrtf(nx), EPS) * fmaxf(sqrtf(nt), EPS);
        g_row_cos[gwarp] = dot / denom;
    }
}

__global__ __launch_bounds__(256) void byol_reduce_kernel(float* __restrict__ out)
{
    __shared__ float sbuf[256];
    int tid = threadIdx.x;

    // Each thread sums 32 strided values — fixed order, deterministic.
    float s = 0.f;
    #pragma unroll
    for (int i = 0; i < NROWS / 256; i++)
        s += g_row_cos[tid + i * 256];
    sbuf[tid] = s;
    __syncthreads();

    #pragma unroll
    for (int stride = 128; stride > 0; stride >>= 1) {
        if (tid < stride) sbuf[tid] += sbuf[tid + stride];
        __syncthreads();
    }

    if (tid == 0)
        out[0] = 2.0f - 2.0f * (sbuf[0] / (float)NROWS);
}

extern "C" void kernel_launch(void* const* d_in, const int* in_sizes, int n_in,
                              void* d_out, int out_size)
{
    const float4* x  = (const float4*)d_in[0];
    const float4* xt = (const float4*)d_in[1];
    float* out = (float*)d_out;

    // 8192 rows, warp per row, 8 warps (256 thr) per block -> 1024 blocks
    byol_rowcos_kernel<<<NROWS / 8, 256>>>(x, xt);
    byol_reduce_kernel<<<1, 256>>>(out);
}